// round 10
// baseline (speedup 1.0000x reference)
#include <cuda_runtime.h>
#include <cstdint>

#define MTOT 8192
#define LW   64      // ww
#define RW   100     // WP*WP
#define CD   128
#define CF   120     // C - SLICE
#define CSTR  104    // conf row stride
#define ASTR  20     // A chunk row stride: banks 20*gid+ctid distinct
#define BSTR  20     // B chunk row stride: same pattern
#define CHUNK_C 16   // channels per chunk (2 k-tiles)
#define NCHUNK 8     // 8 chunks cover 128 ch; k-tile 15 (ch 120..127) not consumed

typedef unsigned int u32;

// Truncation split: hi = top-19-bit truncation (valid tf32 operand),
// lo = exact remainder (FSUB). CVT-free; error ~2^-22.
__device__ __forceinline__ void splitm(float x, u32& hi, u32& lo) {
    u32 h = __float_as_uint(x) & 0xFFFFE000u;
    hi = h;
    lo = __float_as_uint(x - __uint_as_float(h));
}
__device__ __forceinline__ void mma_tf32(float c[4],
                                         u32 a0, u32 a1, u32 a2, u32 a3,
                                         u32 b0, u32 b1) {
    asm volatile(
        "mma.sync.aligned.m16n8k8.row.col.f32.tf32.tf32.f32 "
        "{%0,%1,%2,%3}, {%4,%5,%6,%7}, {%8,%9}, {%0,%1,%2,%3};"
        : "+f"(c[0]), "+f"(c[1]), "+f"(c[2]), "+f"(c[3])
        : "r"(a0), "r"(a1), "r"(a2), "r"(a3), "r"(b0), "r"(b1));
}
__device__ __forceinline__ void cp_async16(u32 smem_addr, const void* gptr) {
    asm volatile("cp.async.ca.shared.global [%0], [%1], 16;\n"
                 :: "r"(smem_addr), "l"(gptr) : "memory");
}
#define CP_COMMIT() asm volatile("cp.async.commit_group;\n" ::: "memory")
#define CP_WAIT(N)  asm volatile("cp.async.wait_group %0;\n" :: "n"(N) : "memory")

// ---- shared memory layout (floats) — 3-buffer stream, ~45 KB/CTA ----
// A bufs: 3 x (64 x 20)   [0, 3840)
// B bufs: 3 x (104 x 20)  [3840, 10080)
// conf (64 x 104 = 6656) aliases [0, 6656) after the mainloop
// ff1  : 100 x 8          [10080, 10880)
// misc : [10880, 11248)
#define OFF_A0   0
#define OFF_B0   3840
#define ABUFSZ   1280
#define BBUFSZ   2080
#define OFF_CONF 0
#define OFF_FF1  10080
#define OFF_RMAX 10880
#define OFF_RINV 10944
#define OFF_CMAX 11008
#define OFF_CINV 11112
#define OFF_REDV 11216
#define OFF_REDI 11232
#define SMEM_FLOATS 11248
#define SMEM_BYTES (SMEM_FLOATS * 4)

__global__ void __launch_bounds__(256, 4)
fine_matching_kernel(const float* __restrict__ feat0,
                     const float* __restrict__ feat1,
                     const float* __restrict__ mk0,
                     const float* __restrict__ mk1,
                     float* __restrict__ out)
{
    extern __shared__ float smem[];
    float* conf = smem + OFF_CONF;
    float* ff1  = smem + OFF_FF1;
    float* rmax = smem + OFF_RMAX;
    float* rinv = smem + OFF_RINV;
    float* cmax = smem + OFF_CMAX;
    float* cinv = smem + OFF_CINV;
    float* redv = smem + OFF_REDV;
    int*   redi = (int*)(smem + OFF_REDI);

    const int m    = blockIdx.x;
    const int tid  = threadIdx.x;
    const int warp = tid >> 5;
    const int lane = tid & 31;

    u32 smem_u32;
    { unsigned long long gp = __cvta_generic_to_shared(smem); smem_u32 = (u32)gp; }

    const float* f0base = feat0 + (size_t)m * (LW * CD);
    const float* f1base = feat1 + (size_t)m * (RW * CD);

    // ---- stage A+B chunk (ck) into buffer slot (buf) ----
    // A: 64 rows x 4 float4 = 256 items (1/thread); B: 104 x 4 = 416 items.
    #define STAGE_AB(buf, ck) do {                                              \
        {                                                                       \
            int _l = tid >> 2, _q = (tid & 3) * 4;                              \
            cp_async16(smem_u32 + (u32)(OFF_A0 + (buf)*ABUFSZ + _l*ASTR + _q)*4, \
                       f0base + _l * CD + (ck) * CHUNK_C + _q);                 \
        }                                                                       \
        for (int _j = tid; _j < 416; _j += 256) {                               \
            int _r = _j >> 2, _q = (_j & 3) * 4;                                \
            cp_async16(smem_u32 + (u32)(OFF_B0 + (buf)*BBUFSZ + _r*BSTR + _q)*4, \
                       f1base + _r * CD + (ck) * CHUNK_C + _q);                 \
        }                                                                       \
    } while (0)

    // prologue: 3 chunks in flight (ff rides with chunk 0's group)
    STAGE_AB(0, 0);
    for (int j = tid; j < 200; j += 256) {
        int r = j >> 1, q = (j & 1) * 4;
        cp_async16(smem_u32 + (u32)(OFF_FF1 + r * 8 + q) * 4,
                   f1base + r * CD + 120 + q);
    }
    CP_COMMIT();
    STAGE_AB(1, 1); CP_COMMIT();
    STAGE_AB(2, 2); CP_COMMIT();
    CP_WAIT(2);             // chunk 0 (+ff) resident
    __syncthreads();

    // ---- tensor-core mainloop: 3xTF32 m16n8k8, 3-buffer pipeline ----
    const int gid  = lane >> 2;      // 0..7
    const int ctid = lane & 3;       // 0..3
    const int wm   = warp & 3;       // M-tile group: l0 = wm*16
    const int wn   = warp >> 2;      // N half
    const int l0   = wm * 16;
    const int nbase = wn * 56;       // wn0: 7 tiles (n 0..55), wn1: 6 (56..103)

    float c[7][4];
    #pragma unroll
    for (int j = 0; j < 7; ++j)
        { c[j][0] = 0.f; c[j][1] = 0.f; c[j][2] = 0.f; c[j][3] = 0.f; }

    const int aOff = (l0 + gid) * ASTR + ctid;
    const int bOff = (nbase + gid) * BSTR + ctid;

    #define BMMA(cj, bp) do {                                                  \
        float _bf0 = (bp)[0];                                                  \
        float _bf1 = (bp)[4];                                                  \
        u32 _bh0, _bl0, _bh1, _bl1;                                            \
        splitm(_bf0, _bh0, _bl0);                                              \
        splitm(_bf1, _bh1, _bl1);                                              \
        mma_tf32(cj, ah0, ah1, ah2, ah3, _bh0, _bh1);                          \
        mma_tf32(cj, ah0, ah1, ah2, ah3, _bl0, _bl1);                          \
        mma_tf32(cj, al0, al1, al2, al3, _bh0, _bh1);                          \
    } while (0)

    #pragma unroll 1
    for (int ck = 0; ck < NCHUNK; ++ck) {
        const int bufs = ck - (ck >= 3 ? 3 : 0) - (ck >= 6 ? 3 : 0);  // ck % 3
        const float* ab = smem + OFF_A0 + bufs * ABUFSZ + aOff;
        const float* bb = smem + OFF_B0 + bufs * BBUFSZ + bOff;
        const int nkt = (ck == NCHUNK - 1) ? 1 : 2;   // ch 120..127 excluded
        #pragma unroll
        for (int kt = 0; kt < 2; ++kt) {
            if (kt < nkt) {
                const float* ap = ab + kt * 8;
                float af0 = ap[0]            * 0.0078125f;
                float af1 = ap[8 * ASTR]     * 0.0078125f;
                float af2 = ap[4]            * 0.0078125f;
                float af3 = ap[8 * ASTR + 4] * 0.0078125f;
                u32 ah0, al0, ah1, al1, ah2, al2, ah3, al3;
                splitm(af0, ah0, al0);
                splitm(af1, ah1, al1);
                splitm(af2, ah2, al2);
                splitm(af3, ah3, al3);
                const float* bbase = bb + kt * 8;
                #pragma unroll
                for (int j = 0; j < 6; ++j)
                    BMMA(c[j], bbase + j * (8 * BSTR));
                if (wn == 0)                      // uniform branch per warp
                    BMMA(c[6], bbase + 6 * (8 * BSTR));
            }
        }
        // ensure next chunk's data has landed (staged 2 chunks ago — usually done)
        if (ck < NCHUNK - 2)      CP_WAIT(1);
        else if (ck == NCHUNK - 2) CP_WAIT(0);
        __syncthreads();          // publish chunk ck+1; release buf ck%3
        if (ck + 3 < NCHUNK) {
            STAGE_AB(bufs, ck + 3);
            CP_COMMIT();
        }
    }
    // mainloop ends with __syncthreads(): all buffer reads complete,
    // conf may now alias the A/B buffer region.

    // ---- store conf from C fragments (cols 100..103 garbage, never read) ----
    {
        const int rowa = (l0 + gid) * CSTR + 2 * ctid;
        const int ntiles = wn ? 6 : 7;
        #pragma unroll
        for (int j = 0; j < 7; ++j) {
            if (j < ntiles) {
                int o = rowa + nbase + 8 * j;
                *(float2*)&conf[o]            = make_float2(c[j][0], c[j][1]);
                *(float2*)&conf[o + 8 * CSTR] = make_float2(c[j][2], c[j][3]);
            }
        }
    }
    __syncthreads();

    // ---- softmax stats, split across warps ----
    if (warp < 4) {
        // row stats (axis=2 over 100 r): warps 0-3, 16 rows each
        #pragma unroll 4
        for (int q = 0; q < 16; ++q) {
            int l = warp * 16 + q;
            const float* row = &conf[l * CSTR];
            float v0 = row[lane], v1 = row[lane + 32], v2 = row[lane + 64];
            float v3 = (lane < 4) ? row[lane + 96] : -1e30f;
            float mx = fmaxf(fmaxf(v0, v1), fmaxf(v2, v3));
            #pragma unroll
            for (int o = 16; o; o >>= 1) mx = fmaxf(mx, __shfl_xor_sync(~0u, mx, o));
            float s = __expf(v0 - mx) + __expf(v1 - mx) + __expf(v2 - mx)
                    + __expf(v3 - mx);
            #pragma unroll
            for (int o = 16; o; o >>= 1) s += __shfl_xor_sync(~0u, s, o);
            if (lane == 0) { rmax[l] = mx; rinv[l] = 1.f / s; }
        }
    } else {
        // col stats (axis=1 over 64 l): warps 4-7, one column per thread
        int r = (warp - 4) * 32 + lane;
        if (r < RW) {
            float m0 = -1e30f, m1 = -1e30f, m2 = -1e30f, m3 = -1e30f;
            #pragma unroll
            for (int l = 0; l < LW; l += 4) {
                m0 = fmaxf(m0, conf[(l + 0) * CSTR + r]);
                m1 = fmaxf(m1, conf[(l + 1) * CSTR + r]);
                m2 = fmaxf(m2, conf[(l + 2) * CSTR + r]);
                m3 = fmaxf(m3, conf[(l + 3) * CSTR + r]);
            }
            float mx = fmaxf(fmaxf(m0, m1), fmaxf(m2, m3));
            float s0 = 0.f, s1 = 0.f, s2 = 0.f, s3 = 0.f;
            #pragma unroll
            for (int l = 0; l < LW; l += 4) {
                s0 += __expf(conf[(l + 0) * CSTR + r] - mx);
                s1 += __expf(conf[(l + 1) * CSTR + r] - mx);
                s2 += __expf(conf[(l + 2) * CSTR + r] - mx);
                s3 += __expf(conf[(l + 3) * CSTR + r] - mx);
            }
            cmax[r] = mx; cinv[r] = 1.f / ((s0 + s1) + (s2 + s3));
        }
    }
    __syncthreads();

    // ---- cropped sm write + argmax (first-occurrence tie-break) ----
    const int rc = tid & 63;
    const int r  = (rc >> 3) * 10 + (rc & 7) + 11;
    const float cm = cmax[r], ci = cinv[r];
    const int lb = tid >> 6;
    float bv = -1e30f; int bi = 0;
    float* outm = out + (size_t)m * 4096;
    #pragma unroll
    for (int e8 = 0; e8 < 16; ++e8) {
        int l = e8 * 4 + lb;
        float v = conf[l * CSTR + r];
        float s = __expf(2.f * v - rmax[l] - cm) * rinv[l] * ci;
        int flat = l * 64 + rc;
        outm[flat] = s;
        if (s > bv) { bv = s; bi = flat; }
    }
    #pragma unroll
    for (int o = 16; o; o >>= 1) {
        float v2 = __shfl_xor_sync(~0u, bv, o);
        int   i2 = __shfl_xor_sync(~0u, bi, o);
        if (v2 > bv || (v2 == bv && i2 < bi)) { bv = v2; bi = i2; }
    }
    if (lane == 0) { redv[warp] = bv; redi[warp] = bi; }
    __syncthreads();

    // ---- warp 0: final reduce + epilogue ----
    if (warp == 0) {
        float v = (lane < 8) ? redv[lane] : -1e30f;
        int   i = (lane < 8) ? redi[lane] : 0x7fffffff;
        #pragma unroll
        for (int o = 4; o; o >>= 1) {
            float v2 = __shfl_xor_sync(~0u, v, o);
            int   i2 = __shfl_xor_sync(~0u, i, o);
            if (v2 > v || (v2 == v && i2 < i)) { v = v2; i = i2; }
        }
        if (lane == 0) {
            int idx = i;
            int il = idx >> 6, ir = idx & 63;
            float dlx = (float)(il & 7) - 3.5f, dly = (float)(il >> 3) - 3.5f;
            float drx = (float)(ir & 7) - 3.5f, dry = (float)(ir >> 3) - 3.5f;

            // last 8 channels of f0 row il, from global (L2-hot)
            float4 av0 = __ldg((const float4*)(f0base + il * CD + CF));
            float4 av1 = __ldg((const float4*)(f0base + il * CD + CF + 4));
            float av[8] = {av0.x, av0.y, av0.z, av0.w, av1.x, av1.y, av1.z, av1.w};

            // 3x3 conf_ff patch from raw ff1; scales folded into the exponent
            float p[9];
            int ib = ir >> 3, jb = ir & 7;
            #pragma unroll
            for (int di = 0; di < 3; ++di) {
                int ii = ib + di - 1; ii = (ii < 0) ? ii + 10 : ((ii > 9) ? ii - 10 : ii);
                #pragma unroll
                for (int dj = 0; dj < 3; ++dj) {
                    int jj = jb + dj - 1; jj = (jj < 0) ? jj + 10 : ((jj > 9) ? jj - 10 : jj);
                    int rr = ii * 10 + jj;
                    float s = 0.f;
                    #pragma unroll
                    for (int t = 0; t < 8; ++t)
                        s += av[t] * ff1[rr * 8 + t];
                    p[di * 3 + dj] = s;
                }
            }
            float mx = p[0];
            #pragma unroll
            for (int t = 1; t < 9; ++t) mx = fmaxf(mx, p[t]);
            const float escale = 0.35355339059327373f * 0.1f;
            float h[9], se = 0.f;
            #pragma unroll
            for (int t = 0; t < 9; ++t) { h[t] = __expf((p[t] - mx) * escale); se += h[t]; }
            float inv = 1.f / se;
            float ex = 0.f, ey = 0.f;
            #pragma unroll
            for (int di = 0; di < 3; ++di)
                #pragma unroll
                for (int dj = 0; dj < 3; ++dj) {
                    ex += h[di * 3 + dj] * (float)(dj - 1);
                    ey += h[di * 3 + dj] * (float)(di - 1);
                }
            ex *= inv; ey *= inv;

            float mk0x = mk0[2 * m], mk0y = mk0[2 * m + 1];
            float mk1x = mk1[2 * m], mk1y = mk1[2 * m + 1];
            size_t base = (size_t)MTOT * 4096;
            out[base + 2 * m]     = mk0x + dlx * 2.f;
            out[base + 2 * m + 1] = mk0y + dly * 2.f;
            out[base + 2 * MTOT + 2 * m]     = mk1x + drx * 2.f + ex * 2.f;
            out[base + 2 * MTOT + 2 * m + 1] = mk1y + dry * 2.f + ey * 2.f;
        }
    }
}

extern "C" void kernel_launch(void* const* d_in, const int* in_sizes, int n_in,
                              void* d_out, int out_size)
{
    const float* feat0 = (const float*)d_in[0];
    const float* feat1 = (const float*)d_in[1];
    const float* mk0   = (const float*)d_in[2];
    const float* mk1   = (const float*)d_in[3];
    float* out = (float*)d_out;

    cudaFuncSetAttribute(fine_matching_kernel,
                         cudaFuncAttributeMaxDynamicSharedMemorySize, SMEM_BYTES);
    fine_matching_kernel<<<MTOT, 256, SMEM_BYTES>>>(feat0, feat1, mk0, mk1, out);
}

// round 11
// speedup vs baseline: 1.1673x; 1.1673x over previous
#include <cuda_runtime.h>
#include <cuda.h>
#include <cstdint>

#define MTOT 8192
#define LW   64      // ww
#define RW   100     // WP*WP
#define CD   128
#define CF   120     // C - SLICE
#define CSTR 104     // conf row stride

typedef unsigned int u32;

// ---- shared memory layout (floats) ----
// buf0: f0 box (64x32=2048) + f1 box (104x32=3328) = 5376   [0, 5376)
// buf1: same                                                [5376, 10752)
// conf (64 x 104 = 6656) aliases [0, 6656) after mainloop.
// f1-box region of buf1 = [7424, 10752) — NOT overlapped by conf; box 3
// (channels 96..127) lives there at epilogue time → ff read in place.
// misc at 10752+.
#define BUFSZ    5376
#define F0BOX    2048
#define OFF_CONF 0
#define OFF_RMAX 10752
#define OFF_RINV 10816
#define OFF_CMAX 10880
#define OFF_CINV 10992
#define OFF_REDV 11104
#define OFF_REDI 11120
#define OFF_MBAR 11136   // 2 mbarriers (2 x 8B = 4 floats)
#define SMEM_FLOATS 11140
#define SMEM_BYTES (SMEM_FLOATS * 4)
#define CHUNK_BYTES ((F0BOX + 3328) * 4)   // 21504

// Truncation split: hi = top-19-bit truncation (valid tf32 operand),
// lo = exact remainder (FSUB). CVT-free; error ~2^-22.
__device__ __forceinline__ void splitm(float x, u32& hi, u32& lo) {
    u32 h = __float_as_uint(x) & 0xFFFFE000u;
    hi = h;
    lo = __float_as_uint(x - __uint_as_float(h));
}
__device__ __forceinline__ void mma_tf32(float c[4],
                                         u32 a0, u32 a1, u32 a2, u32 a3,
                                         u32 b0, u32 b1) {
    asm volatile(
        "mma.sync.aligned.m16n8k8.row.col.f32.tf32.tf32.f32 "
        "{%0,%1,%2,%3}, {%4,%5,%6,%7}, {%8,%9}, {%0,%1,%2,%3};"
        : "+f"(c[0]), "+f"(c[1]), "+f"(c[2]), "+f"(c[3])
        : "r"(a0), "r"(a1), "r"(a2), "r"(a3), "r"(b0), "r"(b1));
}

#define MBAR_INIT(addr, cnt) \
    asm volatile("mbarrier.init.shared.b64 [%0], %1;" :: "r"(addr), "r"(cnt) : "memory")
#define MBAR_EXPECT_TX(addr, bytes) \
    asm volatile("mbarrier.arrive.expect_tx.shared.b64 _, [%0], %1;" :: "r"(addr), "r"(bytes) : "memory")
#define MBAR_WAIT(addr, ph) \
    asm volatile("{\n\t.reg .pred P;\n\tWLP_%=:\n\t" \
        "mbarrier.try_wait.parity.acquire.cta.shared::cta.b64 P, [%0], %1, 0x989680;\n\t" \
        "@P bra.uni WDN_%=;\n\tbra.uni WLP_%=;\n\tWDN_%=:\n\t}" \
        :: "r"(addr), "r"(ph) : "memory")
#define TMA2D(dst, mapp, cx, cy, mbar) \
    asm volatile("cp.async.bulk.tensor.2d.shared::cta.global.tile.mbarrier::complete_tx::bytes " \
        "[%0], [%1, {%2, %3}], [%4];" \
        :: "r"(dst), "l"(mapp), "r"(cx), "r"(cy), "r"(mbar) : "memory")

__global__ void __launch_bounds__(256, 4)
fine_matching_kernel(const float* __restrict__ feat0,
                     const float* __restrict__ feat1,
                     const float* __restrict__ mk0,
                     const float* __restrict__ mk1,
                     float* __restrict__ out,
                     const __grid_constant__ CUtensorMap tmap0,
                     const __grid_constant__ CUtensorMap tmap1)
{
    extern __shared__ float smem[];
    float* conf = smem + OFF_CONF;
    float* rmax = smem + OFF_RMAX;
    float* rinv = smem + OFF_RINV;
    float* cmax = smem + OFF_CMAX;
    float* cinv = smem + OFF_CINV;
    float* redv = smem + OFF_REDV;
    int*   redi = (int*)(smem + OFF_REDI);

    const int m    = blockIdx.x;
    const int tid  = threadIdx.x;
    const int warp = tid >> 5;
    const int lane = tid & 31;

    u32 smem_u32;
    { unsigned long long gp = __cvta_generic_to_shared(smem); smem_u32 = (u32)gp; }
    const u32 mbar0 = smem_u32 + OFF_MBAR * 4;
    const u32 mbar1 = mbar0 + 8;

    const float* f0base = feat0 + (size_t)m * (LW * CD);

    // ---- init mbarriers, then launch chunks 0 and 1 (TMA, SW128 boxes) ----
    if (tid == 0) {
        MBAR_INIT(mbar0, 1);
        MBAR_INIT(mbar1, 1);
    }
    __syncthreads();
    if (tid == 0) {
        MBAR_EXPECT_TX(mbar0, CHUNK_BYTES);
        TMA2D(smem_u32,                    &tmap0, 0,  m * LW, mbar0);
        TMA2D(smem_u32 + F0BOX * 4,        &tmap1, 0,  m * RW, mbar0);
        MBAR_EXPECT_TX(mbar1, CHUNK_BYTES);
        TMA2D(smem_u32 + BUFSZ * 4,          &tmap0, 32, m * LW, mbar1);
        TMA2D(smem_u32 + (BUFSZ+F0BOX) * 4,  &tmap1, 32, m * RW, mbar1);
    }

    // ---- tensor-core mainloop: 3xTF32 m16n8k8 over 4 swizzled k-boxes ----
    const int gid  = lane >> 2;      // 0..7
    const int ctid = lane & 3;       // 0..3
    const int wm   = warp & 3;       // M-tile group: l0 = wm*16
    const int wn   = warp >> 2;      // N half
    const int l0   = wm * 16;
    const int nbase = wn * 56;       // wn0: 7 tiles (n 0..55), wn1: 6 (56..103)
    const int e2   = gid << 2;       // SW128 XOR key (row%8 == gid for our rows)

    float c[7][4];
    #pragma unroll
    for (int j = 0; j < 7; ++j)
        { c[j][0] = 0.f; c[j][1] = 0.f; c[j][2] = 0.f; c[j][3] = 0.f; }

    #define BMMA(cj, bp, x0, x1) do {                                          \
        float _bf0 = (bp)[x0];                                                 \
        float _bf1 = (bp)[x1];                                                 \
        u32 _bh0, _bl0, _bh1, _bl1;                                            \
        splitm(_bf0, _bh0, _bl0);                                              \
        splitm(_bf1, _bh1, _bl1);                                              \
        mma_tf32(cj, ah0, ah1, ah2, ah3, _bh0, _bh1);                          \
        mma_tf32(cj, ah0, ah1, ah2, ah3, _bl0, _bl1);                          \
        mma_tf32(cj, al0, al1, al2, al3, _bh0, _bh1);                          \
    } while (0)

    #pragma unroll 1
    for (int ck = 0; ck < 4; ++ck) {
        const int slot = ck & 1;
        MBAR_WAIT(slot ? mbar1 : mbar0, (ck >> 1) & 1);
        const float* ab = smem + slot * BUFSZ + (l0 + gid) * 32;
        const float* bb = smem + slot * BUFSZ + F0BOX + (nbase + gid) * 32;
        const int nkt = (ck == 3) ? 3 : 4;   // channels 120..127 excluded
        #pragma unroll
        for (int kt = 0; kt < 4; ++kt) {
            if (kt < nkt) {
                const int xk = (kt * 8 + ctid) ^ e2;   // swizzled col
                const int xp = xk ^ 4;
                float af0 = ab[xk]        * 0.0078125f;
                float af1 = ab[256 + xk]  * 0.0078125f;
                float af2 = ab[xp]        * 0.0078125f;
                float af3 = ab[256 + xp]  * 0.0078125f;
                u32 ah0, al0, ah1, al1, ah2, al2, ah3, al3;
                splitm(af0, ah0, al0);
                splitm(af1, ah1, al1);
                splitm(af2, ah2, al2);
                splitm(af3, ah3, al3);
                #pragma unroll
                for (int j = 0; j < 6; ++j)
                    BMMA(c[j], bb + j * 256, xk, xp);
                if (wn == 0)                      // uniform branch per warp
                    BMMA(c[6], bb + 6 * 256, xk, xp);
            }
        }
        __syncthreads();                 // slot fully consumed by all warps
        if (ck < 2 && tid == 0) {
            const u32 mb = slot ? mbar1 : mbar0;
            MBAR_EXPECT_TX(mb, CHUNK_BYTES);
            TMA2D(smem_u32 + slot * BUFSZ * 4,           &tmap0, (ck + 2) * 32, m * LW, mb);
            TMA2D(smem_u32 + (slot * BUFSZ + F0BOX) * 4, &tmap1, (ck + 2) * 32, m * RW, mb);
        }
    }
    // mainloop ends with __syncthreads(): conf may alias [0, 6656).
    // f1 box 3 (buf1 f1 region, [7424,10752)) stays intact for the epilogue.

    // ---- store conf from C fragments (cols 100..103 garbage, never read) ----
    {
        const int rowa = (l0 + gid) * CSTR + 2 * ctid;
        const int ntiles = wn ? 6 : 7;
        #pragma unroll
        for (int j = 0; j < 7; ++j) {
            if (j < ntiles) {
                int o = rowa + nbase + 8 * j;
                *(float2*)&conf[o]            = make_float2(c[j][0], c[j][1]);
                *(float2*)&conf[o + 8 * CSTR] = make_float2(c[j][2], c[j][3]);
            }
        }
    }
    __syncthreads();

    // ---- softmax stats, split across warps ----
    if (warp < 4) {
        // row stats (axis=2 over 100 r): warps 0-3, 16 rows each
        #pragma unroll 4
        for (int q = 0; q < 16; ++q) {
            int l = warp * 16 + q;
            const float* row = &conf[l * CSTR];
            float v0 = row[lane], v1 = row[lane + 32], v2 = row[lane + 64];
            float v3 = (lane < 4) ? row[lane + 96] : -1e30f;
            float mx = fmaxf(fmaxf(v0, v1), fmaxf(v2, v3));
            #pragma unroll
            for (int o = 16; o; o >>= 1) mx = fmaxf(mx, __shfl_xor_sync(~0u, mx, o));
            float s = __expf(v0 - mx) + __expf(v1 - mx) + __expf(v2 - mx)
                    + __expf(v3 - mx);
            #pragma unroll
            for (int o = 16; o; o >>= 1) s += __shfl_xor_sync(~0u, s, o);
            if (lane == 0) { rmax[l] = mx; rinv[l] = 1.f / s; }
        }
    } else {
        // col stats (axis=1 over 64 l): warps 4-7, one column per thread
        int r = (warp - 4) * 32 + lane;
        if (r < RW) {
            float m0 = -1e30f, m1 = -1e30f, m2 = -1e30f, m3 = -1e30f;
            #pragma unroll
            for (int l = 0; l < LW; l += 4) {
                m0 = fmaxf(m0, conf[(l + 0) * CSTR + r]);
                m1 = fmaxf(m1, conf[(l + 1) * CSTR + r]);
                m2 = fmaxf(m2, conf[(l + 2) * CSTR + r]);
                m3 = fmaxf(m3, conf[(l + 3) * CSTR + r]);
            }
            float mx = fmaxf(fmaxf(m0, m1), fmaxf(m2, m3));
            float s0 = 0.f, s1 = 0.f, s2 = 0.f, s3 = 0.f;
            #pragma unroll
            for (int l = 0; l < LW; l += 4) {
                s0 += __expf(conf[(l + 0) * CSTR + r] - mx);
                s1 += __expf(conf[(l + 1) * CSTR + r] - mx);
                s2 += __expf(conf[(l + 2) * CSTR + r] - mx);
                s3 += __expf(conf[(l + 3) * CSTR + r] - mx);
            }
            cmax[r] = mx; cinv[r] = 1.f / ((s0 + s1) + (s2 + s3));
        }
    }
    __syncthreads();

    // ---- cropped sm write + argmax (first-occurrence tie-break) ----
    const int rc = tid & 63;
    const int r  = (rc >> 3) * 10 + (rc & 7) + 11;
    const float cm = cmax[r], ci = cinv[r];
    const int lb = tid >> 6;
    float bv = -1e30f; int bi = 0;
    float* outm = out + (size_t)m * 4096;
    #pragma unroll
    for (int e8 = 0; e8 < 16; ++e8) {
        int l = e8 * 4 + lb;
        float v = conf[l * CSTR + r];
        float s = __expf(2.f * v - rmax[l] - cm) * rinv[l] * ci;
        int flat = l * 64 + rc;
        outm[flat] = s;
        if (s > bv) { bv = s; bi = flat; }
    }
    #pragma unroll
    for (int o = 16; o; o >>= 1) {
        float v2 = __shfl_xor_sync(~0u, bv, o);
        int   i2 = __shfl_xor_sync(~0u, bi, o);
        if (v2 > bv || (v2 == bv && i2 < bi)) { bv = v2; bi = i2; }
    }
    if (lane == 0) { redv[warp] = bv; redi[warp] = bi; }
    __syncthreads();

    // ---- warp 0: final reduce + epilogue ----
    if (warp == 0) {
        float v = (lane < 8) ? redv[lane] : -1e30f;
        int   i = (lane < 8) ? redi[lane] : 0x7fffffff;
        #pragma unroll
        for (int o = 4; o; o >>= 1) {
            float v2 = __shfl_xor_sync(~0u, v, o);
            int   i2 = __shfl_xor_sync(~0u, i, o);
            if (v2 > v || (v2 == v && i2 < i)) { v = v2; i = i2; }
        }
        if (lane == 0) {
            int idx = i;
            int il = idx >> 6, ir = idx & 63;
            float dlx = (float)(il & 7) - 3.5f, dly = (float)(il >> 3) - 3.5f;
            float drx = (float)(ir & 7) - 3.5f, dry = (float)(ir >> 3) - 3.5f;

            // last 8 channels of f0 row il, from global (L2-hot)
            float4 av0 = __ldg((const float4*)(f0base + il * CD + CF));
            float4 av1 = __ldg((const float4*)(f0base + il * CD + CF + 4));
            float av[8] = {av0.x, av0.y, av0.z, av0.w, av1.x, av1.y, av1.z, av1.w};

            // 3x3 conf_ff patch; f1 ff channels read from swizzled box 3
            // (buf1 f1 region): channel 120+t -> box col 24+t.
            const float* ffbox = smem + BUFSZ + F0BOX;
            float p[9];
            int ib = ir >> 3, jb = ir & 7;
            #pragma unroll
            for (int di = 0; di < 3; ++di) {
                int ii = ib + di - 1; ii = (ii < 0) ? ii + 10 : ((ii > 9) ? ii - 10 : ii);
                #pragma unroll
                for (int dj = 0; dj < 3; ++dj) {
                    int jj = jb + dj - 1; jj = (jj < 0) ? jj + 10 : ((jj > 9) ? jj - 10 : jj);
                    int rr = ii * 10 + jj;
                    int eb = (rr & 7) << 2;
                    float s = 0.f;
                    #pragma unroll
                    for (int t = 0; t < 8; ++t)
                        s += av[t] * ffbox[rr * 32 + ((24 + t) ^ eb)];
                    p[di * 3 + dj] = s;
                }
            }
            float mx = p[0];
            #pragma unroll
            for (int t = 1; t < 9; ++t) mx = fmaxf(mx, p[t]);
            const float escale = 0.35355339059327373f * 0.1f;
            float h[9], se = 0.f;
            #pragma unroll
            for (int t = 0; t < 9; ++t) { h[t] = __expf((p[t] - mx) * escale); se += h[t]; }
            float inv = 1.f / se;
            float ex = 0.f, ey = 0.f;
            #pragma unroll
            for (int di = 0; di < 3; ++di)
                #pragma unroll
                for (int dj = 0; dj < 3; ++dj) {
                    ex += h[di * 3 + dj] * (float)(dj - 1);
                    ey += h[di * 3 + dj] * (float)(di - 1);
                }
            ex *= inv; ey *= inv;

            float mk0x = mk0[2 * m], mk0y = mk0[2 * m + 1];
            float mk1x = mk1[2 * m], mk1y = mk1[2 * m + 1];
            size_t base = (size_t)MTOT * 4096;
            out[base + 2 * m]     = mk0x + dlx * 2.f;
            out[base + 2 * m + 1] = mk0y + dly * 2.f;
            out[base + 2 * MTOT + 2 * m]     = mk1x + drx * 2.f + ex * 2.f;
            out[base + 2 * MTOT + 2 * m + 1] = mk1y + dry * 2.f + ey * 2.f;
        }
    }
}

typedef CUresult (*PFN_encodeTiled)(
    CUtensorMap*, CUtensorMapDataType, cuuint32_t, void*,
    const cuuint64_t*, const cuuint64_t*, const cuuint32_t*, const cuuint32_t*,
    CUtensorMapInterleave, CUtensorMapSwizzle, CUtensorMapL2promotion,
    CUtensorMapFloatOOBfill);

extern "C" void kernel_launch(void* const* d_in, const int* in_sizes, int n_in,
                              void* d_out, int out_size)
{
    const float* feat0 = (const float*)d_in[0];
    const float* feat1 = (const float*)d_in[1];
    const float* mk0   = (const float*)d_in[2];
    const float* mk1   = (const float*)d_in[3];
    float* out = (float*)d_out;

    // tensor maps built fresh every call (host-side, no allocation)
    void* fn = nullptr;
    cudaDriverEntryPointQueryResult qres;
    cudaGetDriverEntryPoint("cuTensorMapEncodeTiled", &fn,
                            cudaEnableDefault, &qres);
    PFN_encodeTiled enc = (PFN_encodeTiled)fn;

    CUtensorMap map0, map1;
    {
        cuuint64_t dims[2]  = {CD, (cuuint64_t)MTOT * LW};
        cuuint64_t strd[1]  = {CD * 4};
        cuuint32_t box[2]   = {32, LW};
        cuuint32_t els[2]   = {1, 1};
        enc(&map0, CU_TENSOR_MAP_DATA_TYPE_FLOAT32, 2, (void*)feat0,
            dims, strd, box, els,
            CU_TENSOR_MAP_INTERLEAVE_NONE, CU_TENSOR_MAP_SWIZZLE_128B,
            CU_TENSOR_MAP_L2_PROMOTION_L2_128B, CU_TENSOR_MAP_FLOAT_OOB_FILL_NONE);
    }
    {
        cuuint64_t dims[2]  = {CD, (cuuint64_t)MTOT * RW};
        cuuint64_t strd[1]  = {CD * 4};
        cuuint32_t box[2]   = {32, 104};   // 4-row bleed into next m: harmless
        cuuint32_t els[2]   = {1, 1};
        enc(&map1, CU_TENSOR_MAP_DATA_TYPE_FLOAT32, 2, (void*)feat1,
            dims, strd, box, els,
            CU_TENSOR_MAP_INTERLEAVE_NONE, CU_TENSOR_MAP_SWIZZLE_128B,
            CU_TENSOR_MAP_L2_PROMOTION_L2_128B, CU_TENSOR_MAP_FLOAT_OOB_FILL_NONE);
    }

    cudaFuncSetAttribute(fine_matching_kernel,
                         cudaFuncAttributeMaxDynamicSharedMemorySize, SMEM_BYTES);
    fine_matching_kernel<<<MTOT, 256, SMEM_BYTES>>>(feat0, feat1, mk0, mk1, out,
                                                    map0, map1);
}

// round 12
// speedup vs baseline: 1.3217x; 1.1322x over previous
#include <cuda_runtime.h>
#include <cuda.h>
#include <cstdint>

#define MTOT 8192
#define LW   64      // ww
#define RW   100     // WP*WP
#define CD   128
#define CSTR 104     // conf row stride
#define CROW 12      // converted-array row stride (u32): banks 12g+c distinct

typedef unsigned int u32;

// ---- shared memory layout (floats/u32) ----
// conv bufs: 2 slots x (AH 768 | AL 768 | BH 1248 | BL 1248) = 8064   [0, 8064)
//            conf (64x104 = 6656) aliases [0, 6656) post-mainloop
// raw bufs : 2 slots x (A 64x16 = 1024 | B 104x16 = 1664) = 5376     [8064, 13440)
//            slot1 B box (chunk 7, ch 112..127) survives -> ff source
// misc     : rinv 64 | cinv 128 | redv 8 | redi 8 | mbar 4
#define CVSLOT   4032
#define OFF_RAW  8064
#define RAWSLOT  2688
#define OFF_CONF 0
#define OFF_RINV 13440
#define OFF_CINV 13504
#define OFF_REDV 13632
#define OFF_REDI 13640
#define OFF_MBAR 13648
#define SMEM_FLOATS 13652
#define SMEM_BYTES (SMEM_FLOATS * 4)
#define CHUNK_BYTES ((1024 + 1664) * 4)   // 10752

// bf16 pair split: hi = top-16 truncation (packed via PRMT), lo = exact
// f32 remainder truncated to bf16. Dropped ll + lo-trunc terms ~2^-16.
__device__ __forceinline__ void bfsplit2(float x, float y, u32& hp, u32& lp) {
    u32 bx = __float_as_uint(x), by = __float_as_uint(y);
    u32 hx = bx & 0xFFFF0000u,  hy = by & 0xFFFF0000u;
    float lxf = x - __uint_as_float(hx);
    float lyf = y - __uint_as_float(hy);
    asm("prmt.b32 %0, %1, %2, 0x7632;" : "=r"(hp) : "r"(bx), "r"(by));
    asm("prmt.b32 %0, %1, %2, 0x7632;" : "=r"(lp)
        : "r"(__float_as_uint(lxf)), "r"(__float_as_uint(lyf)));
}
__device__ __forceinline__ void mma_bf16(float c[4],
                                         u32 a0, u32 a1, u32 a2, u32 a3,
                                         u32 b0, u32 b1) {
    asm volatile(
        "mma.sync.aligned.m16n8k16.row.col.f32.bf16.bf16.f32 "
        "{%0,%1,%2,%3}, {%4,%5,%6,%7}, {%8,%9}, {%0,%1,%2,%3};"
        : "+f"(c[0]), "+f"(c[1]), "+f"(c[2]), "+f"(c[3])
        : "r"(a0), "r"(a1), "r"(a2), "r"(a3), "r"(b0), "r"(b1));
}

#define MBAR_INIT(addr, cnt) \
    asm volatile("mbarrier.init.shared.b64 [%0], %1;" :: "r"(addr), "r"(cnt) : "memory")
#define MBAR_EXPECT_TX(addr, bytes) \
    asm volatile("mbarrier.arrive.expect_tx.shared.b64 _, [%0], %1;" :: "r"(addr), "r"(bytes) : "memory")
#define MBAR_WAIT(addr, ph) \
    asm volatile("{\n\t.reg .pred P;\n\tWLP_%=:\n\t" \
        "mbarrier.try_wait.parity.acquire.cta.shared::cta.b64 P, [%0], %1, 0x989680;\n\t" \
        "@P bra.uni WDN_%=;\n\tbra.uni WLP_%=;\n\tWDN_%=:\n\t}" \
        :: "r"(addr), "r"(ph) : "memory")
#define TMA2D(dst, mapp, cx, cy, mbar) \
    asm volatile("cp.async.bulk.tensor.2d.shared::cta.global.tile.mbarrier::complete_tx::bytes " \
        "[%0], [%1, {%2, %3}], [%4];" \
        :: "r"(dst), "l"(mapp), "r"(cx), "r"(cy), "r"(mbar) : "memory")

// SW64 swizzle on byte offsets (TMA boxes are 64B-wide rows)
#define SWZ64(o) ((o) ^ (((o) >> 3) & 0x30))

__global__ void __launch_bounds__(256, 4)
fine_matching_kernel(const float* __restrict__ feat0,
                     const float* __restrict__ feat1,
                     const float* __restrict__ mk0,
                     const float* __restrict__ mk1,
                     float* __restrict__ out,
                     const __grid_constant__ CUtensorMap tmap0,
                     const __grid_constant__ CUtensorMap tmap1)
{
    extern __shared__ float smem[];
    u32*   cv   = (u32*)smem;
    float* conf = smem + OFF_CONF;
    float* rinv = smem + OFF_RINV;
    float* cinv = smem + OFF_CINV;
    float* redv = smem + OFF_REDV;
    int*   redi = (int*)(smem + OFF_REDI);

    const int m    = blockIdx.x;
    const int tid  = threadIdx.x;
    const int warp = tid >> 5;
    const int lane = tid & 31;

    u32 smem_u32;
    { unsigned long long gp = __cvta_generic_to_shared(smem); smem_u32 = (u32)gp; }
    const u32 mbar0 = smem_u32 + OFF_MBAR * 4;
    const u32 mbar1 = mbar0 + 8;

    const float* f0base = feat0 + (size_t)m * (LW * CD);

    if (tid == 0) {
        MBAR_INIT(mbar0, 1);
        MBAR_INIT(mbar1, 1);
    }
    __syncthreads();
    if (tid == 0) {
        MBAR_EXPECT_TX(mbar0, CHUNK_BYTES);
        TMA2D(smem_u32 + OFF_RAW * 4,          &tmap0, 0,  m * LW, mbar0);
        TMA2D(smem_u32 + (OFF_RAW+1024) * 4,   &tmap1, 0,  m * RW, mbar0);
        MBAR_EXPECT_TX(mbar1, CHUNK_BYTES);
        TMA2D(smem_u32 + (OFF_RAW+RAWSLOT) * 4,      &tmap0, 16, m * LW, mbar1);
        TMA2D(smem_u32 + (OFF_RAW+RAWSLOT+1024) * 4, &tmap1, 16, m * RW, mbar1);
    }

    // ---- mainloop: 8 chunks x 16ch; convert f32->split bf16, then mma k16 ----
    const int gid  = lane >> 2;
    const int ctid = lane & 3;
    const int wm   = warp & 3;
    const int wn   = warp >> 2;
    const int l0   = wm * 16;
    const int nbase = wn * 56;

    float c[7][4];
    #pragma unroll
    for (int j = 0; j < 7; ++j)
        { c[j][0] = 0.f; c[j][1] = 0.f; c[j][2] = 0.f; c[j][3] = 0.f; }

    #pragma unroll 1
    for (int ck = 0; ck < 8; ++ck) {
        const int slot = ck & 1;
        MBAR_WAIT(slot ? mbar1 : mbar0, (ck >> 1) & 1);

        // -- convert pass: raw f32 box -> packed bf16 hi/lo (pairs) --
        {
            const char* rawA = (const char*)(smem + OFF_RAW + slot * RAWSLOT);
            const char* rawB = rawA + 1024 * 4;
            u32* AHs = cv + slot * CVSLOT;
            u32* ALs = AHs + 768;
            u32* BHs = AHs + 1536;
            u32* BLs = AHs + 2784;
            const bool lastck = (ck == 7);   // ch 120..127 must be zero
            #pragma unroll
            for (int h = 0; h < 2; ++h) {
                int pa = tid + h * 256;              // 512 A pairs
                int row = pa >> 3, p = pa & 7;
                u32 off = row * 64 + p * 8;
                float2 v = *(const float2*)(rawA + SWZ64(off));
                u32 hp, lp;
                bfsplit2(v.x, v.y, hp, lp);
                if (lastck && p >= 4) { hp = 0u; lp = 0u; }
                AHs[row * CROW + p] = hp;
                ALs[row * CROW + p] = lp;
            }
            #pragma unroll
            for (int h = 0; h < 4; ++h) {
                int pb = tid + h * 256;              // 832 B pairs
                if (pb < 832) {
                    int row = pb >> 3, p = pb & 7;
                    u32 off = row * 64 + p * 8;
                    float2 v = *(const float2*)(rawB + SWZ64(off));
                    u32 hp, lp;
                    bfsplit2(v.x, v.y, hp, lp);
                    if (lastck && p >= 4) { hp = 0u; lp = 0u; }
                    BHs[row * CROW + p] = hp;
                    BLs[row * CROW + p] = lp;
                }
            }
        }
        __syncthreads();   // conv[slot] published; raw[slot] free

        if (ck < 6 && tid == 0) {
            const u32 mb = slot ? mbar1 : mbar0;
            MBAR_EXPECT_TX(mb, CHUNK_BYTES);
            TMA2D(smem_u32 + (OFF_RAW + slot*RAWSLOT) * 4,        &tmap0, (ck+2)*16, m * LW, mb);
            TMA2D(smem_u32 + (OFF_RAW + slot*RAWSLOT + 1024) * 4, &tmap1, (ck+2)*16, m * RW, mb);
        }

        // -- mma: one m16n8k16 step per chunk, 3-term bf16 --
        {
            const u32* AHp = cv + slot * CVSLOT;
            const u32* ALp = AHp + 768;
            const u32* BHp = AHp + 1536;
            const u32* BLp = AHp + 2784;
            const int ar = (l0 + gid) * CROW + ctid;
            u32 ah0 = AHp[ar],      ah1 = AHp[ar + 96];
            u32 ah2 = AHp[ar + 4],  ah3 = AHp[ar + 100];
            u32 al0 = ALp[ar],      al1 = ALp[ar + 96];
            u32 al2 = ALp[ar + 4],  al3 = ALp[ar + 100];
            const int br = (nbase + gid) * CROW + ctid;
            #pragma unroll
            for (int j = 0; j < 6; ++j) {
                int o = br + j * 96;
                u32 bh0 = BHp[o], bh1 = BHp[o + 4];
                u32 bl0 = BLp[o], bl1 = BLp[o + 4];
                mma_bf16(c[j], ah0, ah1, ah2, ah3, bh0, bh1);
                mma_bf16(c[j], ah0, ah1, ah2, ah3, bl0, bl1);
                mma_bf16(c[j], al0, al1, al2, al3, bh0, bh1);
            }
            if (wn == 0) {                    // uniform branch: 7th tile
                int o = br + 6 * 96;
                u32 bh0 = BHp[o], bh1 = BHp[o + 4];
                u32 bl0 = BLp[o], bl1 = BLp[o + 4];
                mma_bf16(c[6], ah0, ah1, ah2, ah3, bh0, bh1);
                mma_bf16(c[6], ah0, ah1, ah2, ah3, bl0, bl1);
                mma_bf16(c[6], al0, al1, al2, al3, bh0, bh1);
            }
        }
    }
    __syncthreads();   // all conv reads done: conf may alias conv region

    // ---- store conf (x 1/128 — exact pow2, moved out of operands) ----
    {
        const float sc = 0.0078125f;
        const int rowa = (l0 + gid) * CSTR + 2 * ctid;
        const int ntiles = wn ? 6 : 7;
        #pragma unroll
        for (int j = 0; j < 7; ++j) {
            if (j < ntiles) {
                int o = rowa + nbase + 8 * j;
                *(float2*)&conf[o]            = make_float2(c[j][0]*sc, c[j][1]*sc);
                *(float2*)&conf[o + 8 * CSTR] = make_float2(c[j][2]*sc, c[j][3]*sc);
            }
        }
    }
    __syncthreads();

    // ---- global Vmax (garbage cols included: softmax shift-invariant) ----
    float vm = -1e30f;
    #pragma unroll
    for (int i = 0; i < 26; ++i) vm = fmaxf(vm, conf[tid + i * 256]);
    #pragma unroll
    for (int o = 16; o; o >>= 1) vm = fmaxf(vm, __shfl_xor_sync(~0u, vm, o));
    if (lane == 0) redv[warp] = vm;
    __syncthreads();
    float vmax = redv[0];
    #pragma unroll
    for (int w = 1; w < 8; ++w) vmax = fmaxf(vmax, redv[w]);

    // ---- E pass (in place) + row sums; cols 100..103 excluded from sums ----
    #pragma unroll 2
    for (int q = 0; q < 8; ++q) {
        int l = warp * 8 + q;
        float* row = &conf[l * CSTR];
        float e0 = __expf(row[lane]      - vmax);
        float e1 = __expf(row[lane + 32] - vmax);
        float e2 = __expf(row[lane + 64] - vmax);
        row[lane]      = e0;
        row[lane + 32] = e1;
        row[lane + 64] = e2;
        float s = e0 + e1 + e2;
        if (lane < 4) {
            float e3 = __expf(row[lane + 96] - vmax);
            row[lane + 96] = e3;
            s += e3;
        }
        #pragma unroll
        for (int o = 16; o; o >>= 1) s += __shfl_xor_sync(~0u, s, o);
        if (lane == 0) rinv[l] = 1.f / s;
    }
    __syncthreads();

    // ---- col sums: 2 threads per column, plain adds (no exp) ----
    {
        int col  = tid >> 1;           // 0..127 (>=100 junk, never read)
        int half = tid & 1;
        float s = 0.f;
        const float* p = &conf[(half * 32) * CSTR + col];
        #pragma unroll 8
        for (int l = 0; l < 32; ++l) s += p[l * CSTR];
        float tot = s + __shfl_xor_sync(~0u, s, 1);
        if (!half) cinv[col] = 1.f / tot;
    }
    __syncthreads();

    // ---- cropped sm write + argmax: s = E^2 * rinv * cinv (no exp) ----
    const int rc = tid & 63;
    const int r  = (rc >> 3) * 10 + (rc & 7) + 11;
    const float ci = cinv[r];
    const int lb = tid >> 6;
    float bv = -1e30f; int bi = 0;
    float* outm = out + (size_t)m * 4096;
    #pragma unroll
    for (int e8 = 0; e8 < 16; ++e8) {
        int l = e8 * 4 + lb;
        float e = conf[l * CSTR + r];
        float s = e * e * rinv[l] * ci;
        int flat = l * 64 + rc;
        outm[flat] = s;
        if (s > bv) { bv = s; bi = flat; }
    }
    #pragma unroll
    for (int o = 16; o; o >>= 1) {
        float v2 = __shfl_xor_sync(~0u, bv, o);
        int   i2 = __shfl_xor_sync(~0u, bi, o);
        if (v2 > bv || (v2 == bv && i2 < bi)) { bv = v2; bi = i2; }
    }
    if (lane == 0) { redv[warp] = bv; redi[warp] = bi; }
    __syncthreads();

    // ---- warp 0: final reduce + epilogue ----
    if (warp == 0) {
        float v = (lane < 8) ? redv[lane] : -1e30f;
        int   i = (lane < 8) ? redi[lane] : 0x7fffffff;
        #pragma unroll
        for (int o = 4; o; o >>= 1) {
            float v2 = __shfl_xor_sync(~0u, v, o);
            int   i2 = __shfl_xor_sync(~0u, i, o);
            if (v2 > v || (v2 == v && i2 < i)) { v = v2; i = i2; }
        }
        if (lane == 0) {
            int idx = i;
            int il = idx >> 6, ir = idx & 63;
            float dlx = (float)(il & 7) - 3.5f, dly = (float)(il >> 3) - 3.5f;
            float drx = (float)(ir & 7) - 3.5f, dry = (float)(ir >> 3) - 3.5f;

            // last 8 channels of f0 row il, from global (L2-hot)
            float4 av0 = __ldg((const float4*)(f0base + il * CD + 120));
            float4 av1 = __ldg((const float4*)(f0base + il * CD + 124));
            float av[8] = {av0.x, av0.y, av0.z, av0.w, av1.x, av1.y, av1.z, av1.w};

            // ff channels from surviving raw box (slot 1 B = ch 112..127):
            // channel 120+t -> box col 8+t, SW64-swizzled.
            const char* ffbox = (const char*)(smem + OFF_RAW + RAWSLOT + 1024);
            float p[9];
            int ib = ir >> 3, jb = ir & 7;
            #pragma unroll
            for (int di = 0; di < 3; ++di) {
                int ii = ib + di - 1; ii = (ii < 0) ? ii + 10 : ((ii > 9) ? ii - 10 : ii);
                #pragma unroll
                for (int dj = 0; dj < 3; ++dj) {
                    int jj = jb + dj - 1; jj = (jj < 0) ? jj + 10 : ((jj > 9) ? jj - 10 : jj);
                    int rr = ii * 10 + jj;
                    float s = 0.f;
                    #pragma unroll
                    for (int t = 0; t < 8; ++t) {
                        u32 off = rr * 64 + (8 + t) * 4;
                        s += av[t] * *(const float*)(ffbox + SWZ64(off));
                    }
                    p[di * 3 + dj] = s;
                }
            }
            float mx = p[0];
            #pragma unroll
            for (int t = 1; t < 9; ++t) mx = fmaxf(mx, p[t]);
            const float escale = 0.35355339059327373f * 0.1f;  // (1/sqrt8)/TEMP
            float h[9], se = 0.f;
            #pragma unroll
            for (int t = 0; t < 9; ++t) { h[t] = __expf((p[t] - mx) * escale); se += h[t]; }
            float inv = 1.f / se;
            float ex = 0.f, ey = 0.f;
            #pragma unroll
            for (int di = 0; di < 3; ++di)
                #pragma unroll
                for (int dj = 0; dj < 3; ++dj) {
                    ex += h[di * 3 + dj] * (float)(dj - 1);
                    ey += h[di * 3 + dj] * (float)(di - 1);
                }
            ex *= inv; ey *= inv;

            float mk0x = mk0[2 * m], mk0y = mk0[2 * m + 1];
            float mk1x = mk1[2 * m], mk1y = mk1[2 * m + 1];
            size_t base = (size_t)MTOT * 4096;
            out[base + 2 * m]     = mk0x + dlx * 2.f;
            out[base + 2 * m + 1] = mk0y + dly * 2.f;
            out[base + 2 * MTOT + 2 * m]     = mk1x + drx * 2.f + ex * 2.f;
            out[base + 2 * MTOT + 2 * m + 1] = mk1y + dry * 2.f + ey * 2.f;
        }
    }
}

typedef CUresult (*PFN_encodeTiled)(
    CUtensorMap*, CUtensorMapDataType, cuuint32_t, void*,
    const cuuint64_t*, const cuuint64_t*, const cuuint32_t*, const cuuint32_t*,
    CUtensorMapInterleave, CUtensorMapSwizzle, CUtensorMapL2promotion,
    CUtensorMapFloatOOBfill);

extern "C" void kernel_launch(void* const* d_in, const int* in_sizes, int n_in,
                              void* d_out, int out_size)
{
    const float* feat0 = (const float*)d_in[0];
    const float* feat1 = (const float*)d_in[1];
    const float* mk0   = (const float*)d_in[2];
    const float* mk1   = (const float*)d_in[3];
    float* out = (float*)d_out;

    void* fn = nullptr;
    cudaDriverEntryPointQueryResult qres;
    cudaGetDriverEntryPoint("cuTensorMapEncodeTiled", &fn,
                            cudaEnableDefault, &qres);
    PFN_encodeTiled enc = (PFN_encodeTiled)fn;

    CUtensorMap map0, map1;
    {
        cuuint64_t dims[2]  = {CD, (cuuint64_t)MTOT * LW};
        cuuint64_t strd[1]  = {CD * 4};
        cuuint32_t box[2]   = {16, LW};
        cuuint32_t els[2]   = {1, 1};
        enc(&map0, CU_TENSOR_MAP_DATA_TYPE_FLOAT32, 2, (void*)feat0,
            dims, strd, box, els,
            CU_TENSOR_MAP_INTERLEAVE_NONE, CU_TENSOR_MAP_SWIZZLE_64B,
            CU_TENSOR_MAP_L2_PROMOTION_L2_128B, CU_TENSOR_MAP_FLOAT_OOB_FILL_NONE);
    }
    {
        cuuint64_t dims[2]  = {CD, (cuuint64_t)MTOT * RW};
        cuuint64_t strd[1]  = {CD * 4};
        cuuint32_t box[2]   = {16, 104};   // 4-row bleed / OOB zero-fill: harmless
        cuuint32_t els[2]   = {1, 1};
        enc(&map1, CU_TENSOR_MAP_DATA_TYPE_FLOAT32, 2, (void*)feat1,
            dims, strd, box, els,
            CU_TENSOR_MAP_INTERLEAVE_NONE, CU_TENSOR_MAP_SWIZZLE_64B,
            CU_TENSOR_MAP_L2_PROMOTION_L2_128B, CU_TENSOR_MAP_FLOAT_OOB_FILL_NONE);
    }

    cudaFuncSetAttribute(fine_matching_kernel,
                         cudaFuncAttributeMaxDynamicSharedMemorySize, SMEM_BYTES);
    fine_matching_kernel<<<MTOT, 256, SMEM_BYTES>>>(feat0, feat1, mk0, mk1, out,
                                                    map0, map1);
}

// round 13
// speedup vs baseline: 1.3234x; 1.0013x over previous
#include <cuda_runtime.h>
#include <cuda.h>
#include <cstdint>

#define MTOT 8192
#define LW   64      // ww
#define RW   100     // WP*WP
#define CD   128
#define CSTR 104     // conf row stride
#define CROW 12      // converted-array row stride (u32): banks 12g+c distinct

typedef unsigned int u32;

// ---- shared memory layout (floats/u32) ----
// conv bufs: 2 slots x (AH 768 | AL 768 | BH 1248 | BL 1248) = 8064   [0, 8064)
//            conf (64x104 = 6656) aliases [0, 6656) post-mainloop
// raw bufs : 2 slots x (A 64x16 = 1024 | B 104x16 = 1664) = 5376     [8064, 13440)
//            slot1 B box (chunk 7, ch 112..127) survives -> ff source
// misc     : rinv 64 | cinv 128 | redv 8 | redi 8 | mbar 4
#define CVSLOT   4032
#define OFF_RAW  8064
#define RAWSLOT  2688
#define OFF_CONF 0
#define OFF_RINV 13440
#define OFF_CINV 13504
#define OFF_REDV 13632
#define OFF_REDI 13640
#define OFF_MBAR 13648
#define SMEM_FLOATS 13652
#define SMEM_BYTES (SMEM_FLOATS * 4)
#define CHUNK_BYTES ((1024 + 1664) * 4)   // 10752

// bf16 pair split: hi = top-16 truncation (packed via PRMT), lo = exact
// f32 remainder truncated to bf16. Dropped ll + lo-trunc terms ~2^-16.
__device__ __forceinline__ void bfsplit2(float x, float y, u32& hp, u32& lp) {
    u32 bx = __float_as_uint(x), by = __float_as_uint(y);
    u32 hx = bx & 0xFFFF0000u,  hy = by & 0xFFFF0000u;
    float lxf = x - __uint_as_float(hx);
    float lyf = y - __uint_as_float(hy);
    asm("prmt.b32 %0, %1, %2, 0x7632;" : "=r"(hp) : "r"(bx), "r"(by));
    asm("prmt.b32 %0, %1, %2, 0x7632;" : "=r"(lp)
        : "r"(__float_as_uint(lxf)), "r"(__float_as_uint(lyf)));
}
__device__ __forceinline__ void mma_bf16(float c[4],
                                         u32 a0, u32 a1, u32 a2, u32 a3,
                                         u32 b0, u32 b1) {
    asm volatile(
        "mma.sync.aligned.m16n8k16.row.col.f32.bf16.bf16.f32 "
        "{%0,%1,%2,%3}, {%4,%5,%6,%7}, {%8,%9}, {%0,%1,%2,%3};"
        : "+f"(c[0]), "+f"(c[1]), "+f"(c[2]), "+f"(c[3])
        : "r"(a0), "r"(a1), "r"(a2), "r"(a3), "r"(b0), "r"(b1));
}

#define MBAR_INIT(addr, cnt) \
    asm volatile("mbarrier.init.shared.b64 [%0], %1;" :: "r"(addr), "r"(cnt) : "memory")
#define MBAR_EXPECT_TX(addr, bytes) \
    asm volatile("mbarrier.arrive.expect_tx.shared.b64 _, [%0], %1;" :: "r"(addr), "r"(bytes) : "memory")
#define MBAR_WAIT(addr, ph) \
    asm volatile("{\n\t.reg .pred P;\n\tWLP_%=:\n\t" \
        "mbarrier.try_wait.parity.acquire.cta.shared::cta.b64 P, [%0], %1, 0x989680;\n\t" \
        "@P bra.uni WDN_%=;\n\tbra.uni WLP_%=;\n\tWDN_%=:\n\t}" \
        :: "r"(addr), "r"(ph) : "memory")
#define TMA2D(dst, mapp, cx, cy, mbar) \
    asm volatile("cp.async.bulk.tensor.2d.shared::cta.global.tile.mbarrier::complete_tx::bytes " \
        "[%0], [%1, {%2, %3}], [%4];" \
        :: "r"(dst), "l"(mapp), "r"(cx), "r"(cy), "r"(mbar) : "memory")

// SW64 swizzle on byte offsets (TMA boxes are 64B-wide rows)
#define SWZ64(o) ((o) ^ (((o) >> 3) & 0x30))

__global__ void __launch_bounds__(256, 4)
fine_matching_kernel(const float* __restrict__ feat0,
                     const float* __restrict__ feat1,
                     const float* __restrict__ mk0,
                     const float* __restrict__ mk1,
                     float* __restrict__ out,
                     const __grid_constant__ CUtensorMap tmap0,
                     const __grid_constant__ CUtensorMap tmap1)
{
    extern __shared__ float smem[];
    u32*   cv   = (u32*)smem;
    float* conf = smem + OFF_CONF;
    float* rinv = smem + OFF_RINV;
    float* cinv = smem + OFF_CINV;
    float* redv = smem + OFF_REDV;
    int*   redi = (int*)(smem + OFF_REDI);

    const int m    = blockIdx.x;
    const int tid  = threadIdx.x;
    const int warp = tid >> 5;
    const int lane = tid & 31;

    u32 smem_u32;
    { unsigned long long gp = __cvta_generic_to_shared(smem); smem_u32 = (u32)gp; }
    const u32 mbar0 = smem_u32 + OFF_MBAR * 4;
    const u32 mbar1 = mbar0 + 8;

    const float* f0base = feat0 + (size_t)m * (LW * CD);

    if (tid == 0) {
        MBAR_INIT(mbar0, 1);
        MBAR_INIT(mbar1, 1);
    }
    __syncthreads();
    if (tid == 0) {
        MBAR_EXPECT_TX(mbar0, CHUNK_BYTES);
        TMA2D(smem_u32 + OFF_RAW * 4,          &tmap0, 0,  m * LW, mbar0);
        TMA2D(smem_u32 + (OFF_RAW+1024) * 4,   &tmap1, 0,  m * RW, mbar0);
        MBAR_EXPECT_TX(mbar1, CHUNK_BYTES);
        TMA2D(smem_u32 + (OFF_RAW+RAWSLOT) * 4,      &tmap0, 16, m * LW, mbar1);
        TMA2D(smem_u32 + (OFF_RAW+RAWSLOT+1024) * 4, &tmap1, 16, m * RW, mbar1);
    }

    // ---- mainloop: 8 chunks x 16ch; convert f32->split bf16, then mma k16 ----
    const int gid  = lane >> 2;
    const int ctid = lane & 3;
    const int wm   = warp & 3;
    const int wn   = warp >> 2;
    const int l0   = wm * 16;
    const int nbase = wn * 56;

    float c[7][4];
    #pragma unroll
    for (int j = 0; j < 7; ++j)
        { c[j][0] = 0.f; c[j][1] = 0.f; c[j][2] = 0.f; c[j][3] = 0.f; }

    #pragma unroll 1
    for (int ck = 0; ck < 8; ++ck) {
        const int slot = ck & 1;
        MBAR_WAIT(slot ? mbar1 : mbar0, (ck >> 1) & 1);

        // -- convert pass: raw f32 box -> packed bf16 hi/lo (pairs) --
        {
            const char* rawA = (const char*)(smem + OFF_RAW + slot * RAWSLOT);
            const char* rawB = rawA + 1024 * 4;
            u32* AHs = cv + slot * CVSLOT;
            u32* ALs = AHs + 768;
            u32* BHs = AHs + 1536;
            u32* BLs = AHs + 2784;
            const bool lastck = (ck == 7);   // ch 120..127 must be zero
            #pragma unroll
            for (int h = 0; h < 2; ++h) {
                int pa = tid + h * 256;              // 512 A pairs
                int row = pa >> 3, p = pa & 7;
                u32 off = row * 64 + p * 8;
                float2 v = *(const float2*)(rawA + SWZ64(off));
                u32 hp, lp;
                bfsplit2(v.x, v.y, hp, lp);
                if (lastck && p >= 4) { hp = 0u; lp = 0u; }
                AHs[row * CROW + p] = hp;
                ALs[row * CROW + p] = lp;
            }
            #pragma unroll
            for (int h = 0; h < 4; ++h) {
                int pb = tid + h * 256;              // 832 B pairs
                if (pb < 832) {
                    int row = pb >> 3, p = pb & 7;
                    u32 off = row * 64 + p * 8;
                    float2 v = *(const float2*)(rawB + SWZ64(off));
                    u32 hp, lp;
                    bfsplit2(v.x, v.y, hp, lp);
                    if (lastck && p >= 4) { hp = 0u; lp = 0u; }
                    BHs[row * CROW + p] = hp;
                    BLs[row * CROW + p] = lp;
                }
            }
        }
        __syncthreads();   // conv[slot] published; raw[slot] free

        if (ck < 6 && tid == 0) {
            const u32 mb = slot ? mbar1 : mbar0;
            MBAR_EXPECT_TX(mb, CHUNK_BYTES);
            TMA2D(smem_u32 + (OFF_RAW + slot*RAWSLOT) * 4,        &tmap0, (ck+2)*16, m * LW, mb);
            TMA2D(smem_u32 + (OFF_RAW + slot*RAWSLOT + 1024) * 4, &tmap1, (ck+2)*16, m * RW, mb);
        }

        // -- mma: one m16n8k16 step per chunk, 3-term bf16 --
        {
            const u32* AHp = cv + slot * CVSLOT;
            const u32* ALp = AHp + 768;
            const u32* BHp = AHp + 1536;
            const u32* BLp = AHp + 2784;
            const int ar = (l0 + gid) * CROW + ctid;
            u32 ah0 = AHp[ar],      ah1 = AHp[ar + 96];
            u32 ah2 = AHp[ar + 4],  ah3 = AHp[ar + 100];
            u32 al0 = ALp[ar],      al1 = ALp[ar + 96];
            u32 al2 = ALp[ar + 4],  al3 = ALp[ar + 100];
            const int br = (nbase + gid) * CROW + ctid;
            #pragma unroll
            for (int j = 0; j < 6; ++j) {
                int o = br + j * 96;
                u32 bh0 = BHp[o], bh1 = BHp[o + 4];
                u32 bl0 = BLp[o], bl1 = BLp[o + 4];
                mma_bf16(c[j], ah0, ah1, ah2, ah3, bh0, bh1);
                mma_bf16(c[j], ah0, ah1, ah2, ah3, bl0, bl1);
                mma_bf16(c[j], al0, al1, al2, al3, bh0, bh1);
            }
            if (wn == 0) {                    // uniform branch: 7th tile
                int o = br + 6 * 96;
                u32 bh0 = BHp[o], bh1 = BHp[o + 4];
                u32 bl0 = BLp[o], bl1 = BLp[o + 4];
                mma_bf16(c[6], ah0, ah1, ah2, ah3, bh0, bh1);
                mma_bf16(c[6], ah0, ah1, ah2, ah3, bl0, bl1);
                mma_bf16(c[6], al0, al1, al2, al3, bh0, bh1);
            }
        }
    }
    __syncthreads();   // all conv reads done: conf may alias conv region

    // ---- store conf (x 1/128 — exact pow2, moved out of operands) ----
    {
        const float sc = 0.0078125f;
        const int rowa = (l0 + gid) * CSTR + 2 * ctid;
        const int ntiles = wn ? 6 : 7;
        #pragma unroll
        for (int j = 0; j < 7; ++j) {
            if (j < ntiles) {
                int o = rowa + nbase + 8 * j;
                *(float2*)&conf[o]            = make_float2(c[j][0]*sc, c[j][1]*sc);
                *(float2*)&conf[o + 8 * CSTR] = make_float2(c[j][2]*sc, c[j][3]*sc);
            }
        }
    }
    __syncthreads();

    // ---- global Vmax (garbage cols included: softmax shift-invariant) ----
    float vm = -1e30f;
    #pragma unroll
    for (int i = 0; i < 26; ++i) vm = fmaxf(vm, conf[tid + i * 256]);
    #pragma unroll
    for (int o = 16; o; o >>= 1) vm = fmaxf(vm, __shfl_xor_sync(~0u, vm, o));
    if (lane == 0) redv[warp] = vm;
    __syncthreads();
    float vmax = redv[0];
    #pragma unroll
    for (int w = 1; w < 8; ++w) vmax = fmaxf(vmax, redv[w]);

    // ---- E pass (in place) + row sums; cols 100..103 excluded from sums ----
    #pragma unroll 2
    for (int q = 0; q < 8; ++q) {
        int l = warp * 8 + q;
        float* row = &conf[l * CSTR];
        float e0 = __expf(row[lane]      - vmax);
        float e1 = __expf(row[lane + 32] - vmax);
        float e2 = __expf(row[lane + 64] - vmax);
        row[lane]      = e0;
        row[lane + 32] = e1;
        row[lane + 64] = e2;
        float s = e0 + e1 + e2;
        if (lane < 4) {
            float e3 = __expf(row[lane + 96] - vmax);
            row[lane + 96] = e3;
            s += e3;
        }
        #pragma unroll
        for (int o = 16; o; o >>= 1) s += __shfl_xor_sync(~0u, s, o);
        if (lane == 0) rinv[l] = 1.f / s;
    }
    __syncthreads();

    // ---- col sums: 2 threads per column, plain adds (no exp) ----
    {
        int col  = tid >> 1;           // 0..127 (>=100 junk, never read)
        int half = tid & 1;
        float s = 0.f;
        const float* p = &conf[(half * 32) * CSTR + col];
        #pragma unroll 8
        for (int l = 0; l < 32; ++l) s += p[l * CSTR];
        float tot = s + __shfl_xor_sync(~0u, s, 1);
        if (!half) cinv[col] = 1.f / tot;
    }
    __syncthreads();

    // ---- cropped sm write + argmax: s = E^2 * rinv * cinv (no exp) ----
    const int rc = tid & 63;
    const int r  = (rc >> 3) * 10 + (rc & 7) + 11;
    const float ci = cinv[r];
    const int lb = tid >> 6;
    float bv = -1e30f; int bi = 0;
    float* outm = out + (size_t)m * 4096;
    #pragma unroll
    for (int e8 = 0; e8 < 16; ++e8) {
        int l = e8 * 4 + lb;
        float e = conf[l * CSTR + r];
        float s = e * e * rinv[l] * ci;
        int flat = l * 64 + rc;
        outm[flat] = s;
        if (s > bv) { bv = s; bi = flat; }
    }
    #pragma unroll
    for (int o = 16; o; o >>= 1) {
        float v2 = __shfl_xor_sync(~0u, bv, o);
        int   i2 = __shfl_xor_sync(~0u, bi, o);
        if (v2 > bv || (v2 == bv && i2 < bi)) { bv = v2; bi = i2; }
    }
    if (lane == 0) { redv[warp] = bv; redi[warp] = bi; }
    __syncthreads();

    // ---- warp 0: final reduce + epilogue ----
    if (warp == 0) {
        float v = (lane < 8) ? redv[lane] : -1e30f;
        int   i = (lane < 8) ? redi[lane] : 0x7fffffff;
        #pragma unroll
        for (int o = 4; o; o >>= 1) {
            float v2 = __shfl_xor_sync(~0u, v, o);
            int   i2 = __shfl_xor_sync(~0u, i, o);
            if (v2 > v || (v2 == v && i2 < i)) { v = v2; i = i2; }
        }
        if (lane == 0) {
            int idx = i;
            int il = idx >> 6, ir = idx & 63;
            float dlx = (float)(il & 7) - 3.5f, dly = (float)(il >> 3) - 3.5f;
            float drx = (float)(ir & 7) - 3.5f, dry = (float)(ir >> 3) - 3.5f;

            // last 8 channels of f0 row il, from global (L2-hot)
            float4 av0 = __ldg((const float4*)(f0base + il * CD + 120));
            float4 av1 = __ldg((const float4*)(f0base + il * CD + 124));
            float av[8] = {av0.x, av0.y, av0.z, av0.w, av1.x, av1.y, av1.z, av1.w};

            // ff channels from surviving raw box (slot 1 B = ch 112..127):
            // channel 120+t -> box col 8+t, SW64-swizzled.
            const char* ffbox = (const char*)(smem + OFF_RAW + RAWSLOT + 1024);
            float p[9];
            int ib = ir >> 3, jb = ir & 7;
            #pragma unroll
            for (int di = 0; di < 3; ++di) {
                int ii = ib + di - 1; ii = (ii < 0) ? ii + 10 : ((ii > 9) ? ii - 10 : ii);
                #pragma unroll
                for (int dj = 0; dj < 3; ++dj) {
                    int jj = jb + dj - 1; jj = (jj < 0) ? jj + 10 : ((jj > 9) ? jj - 10 : jj);
                    int rr = ii * 10 + jj;
                    float s = 0.f;
                    #pragma unroll
                    for (int t = 0; t < 8; ++t) {
                        u32 off = rr * 64 + (8 + t) * 4;
                        s += av[t] * *(const float*)(ffbox + SWZ64(off));
                    }
                    p[di * 3 + dj] = s;
                }
            }
            float mx = p[0];
            #pragma unroll
            for (int t = 1; t < 9; ++t) mx = fmaxf(mx, p[t]);
            const float escale = 0.35355339059327373f * 0.1f;  // (1/sqrt8)/TEMP
            float h[9], se = 0.f;
            #pragma unroll
            for (int t = 0; t < 9; ++t) { h[t] = __expf((p[t] - mx) * escale); se += h[t]; }
            float inv = 1.f / se;
            float ex = 0.f, ey = 0.f;
            #pragma unroll
            for (int di = 0; di < 3; ++di)
                #pragma unroll
                for (int dj = 0; dj < 3; ++dj) {
                    ex += h[di * 3 + dj] * (float)(dj - 1);
                    ey += h[di * 3 + dj] * (float)(di - 1);
                }
            ex *= inv; ey *= inv;

            float mk0x = mk0[2 * m], mk0y = mk0[2 * m + 1];
            float mk1x = mk1[2 * m], mk1y = mk1[2 * m + 1];
            size_t base = (size_t)MTOT * 4096;
            out[base + 2 * m]     = mk0x + dlx * 2.f;
            out[base + 2 * m + 1] = mk0y + dly * 2.f;
            out[base + 2 * MTOT + 2 * m]     = mk1x + drx * 2.f + ex * 2.f;
            out[base + 2 * MTOT + 2 * m + 1] = mk1y + dry * 2.f + ey * 2.f;
        }
    }
}

typedef CUresult (*PFN_encodeTiled)(
    CUtensorMap*, CUtensorMapDataType, cuuint32_t, void*,
    const cuuint64_t*, const cuuint64_t*, const cuuint32_t*, const cuuint32_t*,
    CUtensorMapInterleave, CUtensorMapSwizzle, CUtensorMapL2promotion,
    CUtensorMapFloatOOBfill);

extern "C" void kernel_launch(void* const* d_in, const int* in_sizes, int n_in,
                              void* d_out, int out_size)
{
    const float* feat0 = (const float*)d_in[0];
    const float* feat1 = (const float*)d_in[1];
    const float* mk0   = (const float*)d_in[2];
    const float* mk1   = (const float*)d_in[3];
    float* out = (float*)d_out;

    void* fn = nullptr;
    cudaDriverEntryPointQueryResult qres;
    cudaGetDriverEntryPoint("cuTensorMapEncodeTiled", &fn,
                            cudaEnableDefault, &qres);
    PFN_encodeTiled enc = (PFN_encodeTiled)fn;

    CUtensorMap map0, map1;
    {
        cuuint64_t dims[2]  = {CD, (cuuint64_t)MTOT * LW};
        cuuint64_t strd[1]  = {CD * 4};
        cuuint32_t box[2]   = {16, LW};
        cuuint32_t els[2]   = {1, 1};
        enc(&map0, CU_TENSOR_MAP_DATA_TYPE_FLOAT32, 2, (void*)feat0,
            dims, strd, box, els,
            CU_TENSOR_MAP_INTERLEAVE_NONE, CU_TENSOR_MAP_SWIZZLE_64B,
            CU_TENSOR_MAP_L2_PROMOTION_L2_128B, CU_TENSOR_MAP_FLOAT_OOB_FILL_NONE);
    }
    {
        cuuint64_t dims[2]  = {CD, (cuuint64_t)MTOT * RW};
        cuuint64_t strd[1]  = {CD * 4};
        cuuint32_t box[2]   = {16, 104};   // 4-row bleed / OOB zero-fill: harmless
        cuuint32_t els[2]   = {1, 1};
        enc(&map1, CU_TENSOR_MAP_DATA_TYPE_FLOAT32, 2, (void*)feat1,
            dims, strd, box, els,
            CU_TENSOR_MAP_INTERLEAVE_NONE, CU_TENSOR_MAP_SWIZZLE_64B,
            CU_TENSOR_MAP_L2_PROMOTION_L2_128B, CU_TENSOR_MAP_FLOAT_OOB_FILL_NONE);
    }

    cudaFuncSetAttribute(fine_matching_kernel,
                         cudaFuncAttributeMaxDynamicSharedMemorySize, SMEM_BYTES);
    fine_matching_kernel<<<MTOT, 256, SMEM_BYTES>>>(feat0, feat1, mk0, mk1, out,
                                                    map0, map1);
}